// round 7
// baseline (speedup 1.0000x reference)
#include <cuda_runtime.h>
#include <stdint.h>
#include <cub/block/block_radix_sort.cuh>

// Shapes (fixed): seq (16,4096,1024) f32, attn_weights (16,4096) f32,
// out (16,2049,1024) f32.
#define BB 16
#define NN 4096
#define DD 1024
#define KK 2048
#define D4 (DD / 4)
#define CHUNK 512                     // elements per chunk-sort CTA
#define NRUNS (NN / CHUNK)            // 8 sorted runs per batch
#define GROUP 16                      // rows per copy CTA
#define SELGROUPS (KK / GROUP)        // 128 copy CTAs per batch
#define PR_GROUP 64                   // rows per pruned-sum CTA
#define PRCH (KK / PR_GROUP)          // 32 pruned partials per batch

typedef unsigned long long u64;

__device__ u64   g_run[BB * NN];               // chunk-sorted composite keys
__device__ int   g_sorted[BB * NN];
__device__ float g_partial[BB * PRCH * DD];    // 2 MB scratch

// ---------------------------------------------------------------------------
// S1: sort 8 chunks of 512 per batch. Grid (8, BB) = 128 CTAs.
// Key = ~mono(f32) (ascending u32 == descending weight); CUB stable sort
// preserves ascending index on ties. Packed u64 = (key<<32)|idx gives the
// rank kernel a single unique comparison value; composite order matches
// jax.lax.top_k (desc value, asc index on ties).
// ---------------------------------------------------------------------------
__global__ __launch_bounds__(256) void sort_chunks_kernel(const float* __restrict__ w) {
    typedef cub::BlockRadixSort<unsigned int, 256, 2, int> Sorter;
    __shared__ typename Sorter::TempStorage temp;

    const int b = blockIdx.y;
    const int c = blockIdx.x;
    const int t = threadIdx.x;

    unsigned int keys[2];
    int vals[2];
#pragma unroll
    for (int p = 0; p < 2; p++) {
        int i = c * CHUNK + 2 * t + p;
        unsigned int u = __float_as_uint(w[b * NN + i]);
        unsigned int mono = (u & 0x80000000u) ? ~u : (u | 0x80000000u);
        keys[p] = ~mono;
        vals[p] = i;
    }

    Sorter(temp).Sort(keys, vals);   // stable, blocked arrangement

#pragma unroll
    for (int p = 0; p < 2; p++)
        g_run[b * NN + c * CHUNK + 2 * t + p] =
            ((u64)keys[p] << 32) | (unsigned int)vals[p];
}

// ---------------------------------------------------------------------------
// S2: rank + scatter. Each thread owns one element of one run; final rank =
// local pos + sum over the 7 other runs of count(< key), via 7 interleaved
// branchless fixed-step binary searches (9 rounds, MLP=7). Then scatter.
// ---------------------------------------------------------------------------
__global__ __launch_bounds__(256) void rank_scatter_kernel() {
    const int b = blockIdx.y;
    const int i = blockIdx.x * 256 + threadIdx.x;   // 0..4095
    const int r = i >> 9;                            // owning run
    const int p = i & (CHUNK - 1);                   // pos within run

    const u64* base = g_run + b * NN;
    const u64 key = base[i];

    const u64* A[7];
    int c[7];
#pragma unroll
    for (int q = 0; q < 7; q++) {
        A[q] = base + (((r + 1 + q) & 7) << 9);
        c[q] = 0;
    }

#pragma unroll
    for (int step = CHUNK / 2; step > 0; step >>= 1) {
        u64 v[7];
#pragma unroll
        for (int q = 0; q < 7; q++) v[q] = __ldg(A[q] + c[q] + step - 1);
#pragma unroll
        for (int q = 0; q < 7; q++) if (v[q] < key) c[q] += step;
    }

    int rank = p;
#pragma unroll
    for (int q = 0; q < 7; q++) rank += c[q];
    g_sorted[b * NN + rank] = (int)(key & 0xFFFFFFFFu);
}

// ---------------------------------------------------------------------------
// Fused gather/sum, asymmetric grid: per batch, blocks [0,PRCH) each sum 64
// pruned rows into one partial (launched first -- they run longest);
// blocks [PRCH, PRCH+SELGROUPS) each copy 16 selected rows to the output.
// Every seq byte read exactly once; streaming loads/stores (data >> L2).
// 256 threads = one float4 column lane each.
// ---------------------------------------------------------------------------
__global__ __launch_bounds__(256) void gather_sum_kernel(const float4* __restrict__ seq,
                                                         float4* __restrict__ out) {
    const int b = blockIdx.y;
    const int g = blockIdx.x;
    const int tid = threadIdx.x;

    const float4* sb = seq + (size_t)b * NN * D4;

    if (g < PRCH) {
        // pruned-sum CTA: tokens at sorted positions [KK + g*64, KK + g*64 + 64)
        __shared__ int toks[PR_GROUP];
        if (tid < PR_GROUP) toks[tid] = g_sorted[b * NN + KK + g * PR_GROUP + tid];
        __syncthreads();

        float4 acc = make_float4(0.f, 0.f, 0.f, 0.f);
#pragma unroll 8
        for (int t = 0; t < PR_GROUP; t++) {
            float4 v = __ldcs(sb + (size_t)toks[t] * D4 + tid);
            acc.x += v.x; acc.y += v.y; acc.z += v.z; acc.w += v.w;
        }
        float4* part = reinterpret_cast<float4*>(g_partial);
        part[((size_t)b * PRCH + g) * D4 + tid] = acc;
    } else {
        // copy CTA: sorted positions [j0, j0+16)
        const int j0 = (g - PRCH) * GROUP;
        __shared__ int toks[GROUP];
        if (tid < GROUP) toks[tid] = g_sorted[b * NN + j0 + tid];
        __syncthreads();

        float4* dst = out + ((size_t)b * (KK + 1) + j0) * D4 + tid;
#pragma unroll
        for (int h = 0; h < 2; h++) {
            float4 v[8];
#pragma unroll
            for (int t = 0; t < 8; t++)
                v[t] = __ldcs(sb + (size_t)toks[h * 8 + t] * D4 + tid);
#pragma unroll
            for (int t = 0; t < 8; t++)
                __stcs(dst + (size_t)(h * 8 + t) * D4, v[t]);
        }
    }
}

// ---------------------------------------------------------------------------
// Reduce PRCH=32 partials -> mix token (row KK). Grid (4, BB), full unroll
// so all 32 strided (coalesced-per-warp) loads are in flight at once.
// ---------------------------------------------------------------------------
__global__ __launch_bounds__(256) void final_mix_kernel(float* __restrict__ out) {
    const int b = blockIdx.y;
    const int d = blockIdx.x * 256 + threadIdx.x;
    const float* part = g_partial + (size_t)b * PRCH * DD + d;

    float v[PRCH];
#pragma unroll
    for (int c = 0; c < PRCH; c++) v[c] = __ldg(part + (size_t)c * DD);

    float acc = 0.f;
#pragma unroll
    for (int c = 0; c < PRCH; c++) acc += v[c];

    const float scale = 0.05f / (2048.0f + 1e-10f);
    out[((size_t)b * (KK + 1) + KK) * DD + d] = acc * scale;
}

// ---------------------------------------------------------------------------
extern "C" void kernel_launch(void* const* d_in, const int* in_sizes, int n_in,
                              void* d_out, int out_size) {
    const float* seq = (const float*)d_in[0];
    const float* attn_weights = (const float*)d_in[1];
    float* out = (float*)d_out;
    (void)in_sizes; (void)n_in; (void)out_size;

    dim3 sgrid(NRUNS, BB);                // (8, 16)
    sort_chunks_kernel<<<sgrid, 256>>>(attn_weights);

    dim3 rgrid(NN / 256, BB);             // (16, 16)
    rank_scatter_kernel<<<rgrid, 256>>>();

    dim3 fgrid(PRCH + SELGROUPS, BB);     // (160, 16)
    gather_sum_kernel<<<fgrid, 256>>>((const float4*)seq, (float4*)out);

    dim3 xgrid(4, BB);
    final_mix_kernel<<<xgrid, 256>>>(out);
}

// round 8
// speedup vs baseline: 1.0600x; 1.0600x over previous
#include <cuda_runtime.h>
#include <stdint.h>
#include <cub/block/block_radix_sort.cuh>

// Shapes (fixed): seq (16,4096,1024) f32, attn_weights (16,4096) f32,
// out (16,2049,1024) f32.
#define BB 16
#define NN 4096
#define DD 1024
#define KK 2048
#define D4 (DD / 4)
#define CHUNK 1024                    // elements per chunk-sort CTA
#define NRUNS (NN / CHUNK)            // 4 sorted runs per batch
#define GROUP 16                      // rows per copy CTA
#define SELGROUPS (KK / GROUP)        // 128 copy CTAs per batch
#define PR_GROUP 64                   // rows per pruned-sum CTA
#define PRCH (KK / PR_GROUP)          // 32 pruned partials per batch

typedef unsigned long long u64;

__device__ u64   g_run[BB * NN];               // chunk-sorted composite keys
__device__ int   g_sorted[BB * NN];
__device__ float g_partial[BB * PRCH * DD];    // 2 MB scratch
__device__ int   g_count[BB];                  // last-block tickets (self-resetting)

// ---------------------------------------------------------------------------
// S1: sort 4 chunks of 1024 per batch. Grid (4, BB) = 64 CTAs.
// Key = ~mono(f32) (ascending u32 == descending weight); CUB stable sort
// preserves ascending index on ties. Packed u64 = (key<<32)|idx gives the
// rank kernel a unique comparison value; composite order == jax.lax.top_k
// order (desc value, asc index on ties).
// ---------------------------------------------------------------------------
__global__ __launch_bounds__(256) void sort_chunks_kernel(const float* __restrict__ w) {
    typedef cub::BlockRadixSort<unsigned int, 256, 4, int> Sorter;
    __shared__ typename Sorter::TempStorage temp;

    const int b = blockIdx.y;
    const int c = blockIdx.x;
    const int t = threadIdx.x;

    unsigned int keys[4];
    int vals[4];
#pragma unroll
    for (int p = 0; p < 4; p++) {
        int i = c * CHUNK + 4 * t + p;
        unsigned int u = __float_as_uint(w[b * NN + i]);
        unsigned int mono = (u & 0x80000000u) ? ~u : (u | 0x80000000u);
        keys[p] = ~mono;
        vals[p] = i;
    }

    Sorter(temp).Sort(keys, vals);   // stable, blocked arrangement

#pragma unroll
    for (int p = 0; p < 4; p++)
        g_run[b * NN + c * CHUNK + 4 * t + p] =
            ((u64)keys[p] << 32) | (unsigned int)vals[p];
}

// ---------------------------------------------------------------------------
// S2: rank + scatter. Each thread owns one element of one run; final rank =
// local pos + sum over the other 3 runs of count(< key), via 3 interleaved
// branchless fixed-step binary searches (10 rounds, MLP=3). Then scatter.
// ---------------------------------------------------------------------------
__global__ __launch_bounds__(256) void rank_scatter_kernel() {
    const int b = blockIdx.y;
    const int i = blockIdx.x * 256 + threadIdx.x;   // 0..4095
    const int r = i >> 10;                           // owning run
    const int p = i & (CHUNK - 1);                   // pos within run

    const u64* base = g_run + b * NN;
    const u64 key = base[i];

    const u64* A0 = base + (((r + 1) & 3) << 10);
    const u64* A1 = base + (((r + 2) & 3) << 10);
    const u64* A2 = base + (((r + 3) & 3) << 10);

    int c0 = 0, c1 = 0, c2 = 0;
#pragma unroll
    for (int step = CHUNK / 2; step > 0; step >>= 1) {
        u64 v0 = __ldg(A0 + c0 + step - 1);
        u64 v1 = __ldg(A1 + c1 + step - 1);
        u64 v2 = __ldg(A2 + c2 + step - 1);
        if (v0 < key) c0 += step;
        if (v1 < key) c1 += step;
        if (v2 < key) c2 += step;
    }

    const int rank = p + c0 + c1 + c2;
    g_sorted[b * NN + rank] = (int)(key & 0xFFFFFFFFu);
}

// ---------------------------------------------------------------------------
// Fused gather/sum/mix, asymmetric grid: per batch, blocks [0,PRCH) each sum
// 64 pruned rows into one partial (launched first -- they run longest); the
// last-arriving sum CTA per batch reduces the 32 partials (L2-resident) into
// the mix row. Blocks [PRCH, PRCH+SELGROUPS) copy 16 selected rows each.
// Every seq byte read exactly once; streaming loads/stores (data >> L2).
// Deterministic: fixed partial decomposition, fixed reduction loop order.
// ---------------------------------------------------------------------------
__global__ __launch_bounds__(256) void gather_sum_kernel(const float4* __restrict__ seq,
                                                         float4* __restrict__ out) {
    const int b = blockIdx.y;
    const int g = blockIdx.x;
    const int tid = threadIdx.x;

    const float4* sb = seq + (size_t)b * NN * D4;

    if (g < PRCH) {
        // pruned-sum CTA: tokens at sorted positions [KK + g*64, KK + (g+1)*64)
        __shared__ int toks[PR_GROUP];
        __shared__ int ticket;
        if (tid < PR_GROUP) toks[tid] = g_sorted[b * NN + KK + g * PR_GROUP + tid];
        __syncthreads();

        float4 acc = make_float4(0.f, 0.f, 0.f, 0.f);
#pragma unroll 8
        for (int t = 0; t < PR_GROUP; t++) {
            float4 v = __ldcs(sb + (size_t)toks[t] * D4 + tid);
            acc.x += v.x; acc.y += v.y; acc.z += v.z; acc.w += v.w;
        }
        float4* part = reinterpret_cast<float4*>(g_partial);
        part[((size_t)b * PRCH + g) * D4 + tid] = acc;

        // last-block reduction
        __threadfence();
        if (tid == 0) ticket = atomicAdd(&g_count[b], 1);
        __syncthreads();
        if (ticket == PRCH - 1) {
            const float4* pbase = part + (size_t)b * PRCH * D4 + tid;
            float4 s = make_float4(0.f, 0.f, 0.f, 0.f);
#pragma unroll
            for (int c = 0; c < PRCH; c++) {
                float4 v = __ldcg(pbase + (size_t)c * D4);
                s.x += v.x; s.y += v.y; s.z += v.z; s.w += v.w;
            }
            const float scale = 0.05f / (2048.0f + 1e-10f);
            s.x *= scale; s.y *= scale; s.z *= scale; s.w *= scale;
            out[((size_t)b * (KK + 1) + KK) * D4 + tid] = s;
            if (tid == 0) g_count[b] = 0;   // reset for next graph replay
        }
    } else {
        // copy CTA: sorted positions [j0, j0+16)
        const int j0 = (g - PRCH) * GROUP;
        __shared__ int toks[GROUP];
        if (tid < GROUP) toks[tid] = g_sorted[b * NN + j0 + tid];
        __syncthreads();

        float4* dst = out + ((size_t)b * (KK + 1) + j0) * D4 + tid;
#pragma unroll
        for (int h = 0; h < 2; h++) {
            float4 v[8];
#pragma unroll
            for (int t = 0; t < 8; t++)
                v[t] = __ldcs(sb + (size_t)toks[h * 8 + t] * D4 + tid);
#pragma unroll
            for (int t = 0; t < 8; t++)
                __stcs(dst + (size_t)(h * 8 + t) * D4, v[t]);
        }
    }
}

// ---------------------------------------------------------------------------
extern "C" void kernel_launch(void* const* d_in, const int* in_sizes, int n_in,
                              void* d_out, int out_size) {
    const float* seq = (const float*)d_in[0];
    const float* attn_weights = (const float*)d_in[1];
    float* out = (float*)d_out;
    (void)in_sizes; (void)n_in; (void)out_size;

    dim3 sgrid(NRUNS, BB);                // (4, 16)
    sort_chunks_kernel<<<sgrid, 256>>>(attn_weights);

    dim3 rgrid(NN / 256, BB);             // (16, 16)
    rank_scatter_kernel<<<rgrid, 256>>>();

    dim3 fgrid(PRCH + SELGROUPS, BB);     // (160, 16)
    gather_sum_kernel<<<fgrid, 256>>>((const float4*)seq, (float4*)out);
}

// round 9
// speedup vs baseline: 1.0826x; 1.0214x over previous
#include <cuda_runtime.h>
#include <stdint.h>
#include <cub/block/block_radix_sort.cuh>

// Shapes (fixed): seq (16,4096,1024) f32, attn_weights (16,4096) f32,
// out (16,2049,1024) f32.
#define BB 16
#define NN 4096
#define DD 1024
#define KK 2048
#define D4 (DD / 4)
#define CHUNK 1024                    // elements per chunk-sort CTA
#define NRUNS (NN / CHUNK)            // 4 sorted runs per batch
#define GROUP 16                      // rows per copy CTA
#define SELGROUPS (KK / GROUP)        // 128 copy CTAs per batch
#define PR_GROUP 64                   // rows per pruned-sum CTA
#define PRCH (KK / PR_GROUP)          // 32 pruned partials per batch

typedef unsigned long long u64;

__device__ u64   g_run[BB * NN];               // chunk-sorted composite keys
__device__ int   g_sorted[BB * NN];
__device__ float g_partial[BB * PRCH * DD];    // 2 MB scratch
__device__ int   g_count[BB];                  // last-block tickets (self-resetting)

// ---------------------------------------------------------------------------
// S1: sort 4 chunks of 1024 per batch. Grid (4, BB) = 64 CTAs.
// Key = ~mono(f32) (ascending u32 == descending weight); CUB stable sort
// preserves ascending index on ties. Packed u64 = (key<<32)|idx gives the
// rank kernel a unique comparison value; composite order == jax.lax.top_k
// order (desc value, asc index on ties). RADIX_BITS=5 -> 7 passes (not 8).
// ---------------------------------------------------------------------------
__global__ __launch_bounds__(256) void sort_chunks_kernel(const float* __restrict__ w) {
    typedef cub::BlockRadixSort<unsigned int, 256, 4, int, 5> Sorter;
    __shared__ typename Sorter::TempStorage temp;

    const int b = blockIdx.y;
    const int c = blockIdx.x;
    const int t = threadIdx.x;

    unsigned int keys[4];
    int vals[4];
#pragma unroll
    for (int p = 0; p < 4; p++) {
        int i = c * CHUNK + 4 * t + p;
        unsigned int u = __float_as_uint(w[b * NN + i]);
        unsigned int mono = (u & 0x80000000u) ? ~u : (u | 0x80000000u);
        keys[p] = ~mono;
        vals[p] = i;
    }

    Sorter(temp).Sort(keys, vals);   // stable, blocked arrangement

#pragma unroll
    for (int p = 0; p < 4; p++)
        g_run[b * NN + c * CHUNK + 4 * t + p] =
            ((u64)keys[p] << 32) | (unsigned int)vals[p];
}

// ---------------------------------------------------------------------------
// S2: rank + scatter, shared-memory staged. Each CTA first copies ALL 4 runs
// of its batch (32 KB) into smem, then each thread ranks one element:
// rank = local pos + sum over the other 3 runs of exact count(< key), via 3
// interleaved fixed-step binary searches PLUS a final correction probe
// (handles the count==1024 case exactly -> bit-exact lower_bound).
// ---------------------------------------------------------------------------
__global__ __launch_bounds__(256) void rank_scatter_kernel() {
    __shared__ u64 runs[NN];    // 32 KB: all 4 runs of this batch
    const int b = blockIdx.y;
    const int i = blockIdx.x * 256 + threadIdx.x;   // 0..4095

    const u64* base = g_run + b * NN;
#pragma unroll
    for (int s = 0; s < NN / 256; s++)
        runs[threadIdx.x + s * 256] = base[threadIdx.x + s * 256];
    __syncthreads();

    const int r = i >> 10;                           // owning run
    const int p = i & (CHUNK - 1);                   // pos within run
    const u64 key = runs[i];

    const u64* A0 = runs + (((r + 1) & 3) << 10);
    const u64* A1 = runs + (((r + 2) & 3) << 10);
    const u64* A2 = runs + (((r + 3) & 3) << 10);

    int c0 = 0, c1 = 0, c2 = 0;
#pragma unroll
    for (int step = CHUNK / 2; step > 0; step >>= 1) {
        if (A0[c0 + step - 1] < key) c0 += step;
        if (A1[c1 + step - 1] < key) c1 += step;
        if (A2[c2 + step - 1] < key) c2 += step;
    }
    // correction: fixed-step sums to 1023; count may be 1024 (all smaller)
    if (A0[c0] < key) c0++;
    if (A1[c1] < key) c1++;
    if (A2[c2] < key) c2++;

    const int rank = p + c0 + c1 + c2;
    g_sorted[b * NN + rank] = (int)(key & 0xFFFFFFFFu);
}

// ---------------------------------------------------------------------------
// Fused gather/sum/mix, asymmetric grid: per batch, blocks [0,PRCH) each sum
// 64 pruned rows into one partial (launched first -- they run longest); the
// last-arriving sum CTA per batch reduces the 32 partials (L2-resident) into
// the mix row. Blocks [PRCH, PRCH+SELGROUPS) copy 16 selected rows each.
// Every seq byte read exactly once; streaming loads/stores (data >> L2).
// Deterministic: fixed partial decomposition, fixed reduction loop order.
// ---------------------------------------------------------------------------
__global__ __launch_bounds__(256) void gather_sum_kernel(const float4* __restrict__ seq,
                                                         float4* __restrict__ out) {
    const int b = blockIdx.y;
    const int g = blockIdx.x;
    const int tid = threadIdx.x;

    const float4* sb = seq + (size_t)b * NN * D4;

    if (g < PRCH) {
        // pruned-sum CTA: tokens at sorted positions [KK + g*64, KK + (g+1)*64)
        __shared__ int toks[PR_GROUP];
        __shared__ int ticket;
        if (tid < PR_GROUP) toks[tid] = g_sorted[b * NN + KK + g * PR_GROUP + tid];
        __syncthreads();

        float4 acc = make_float4(0.f, 0.f, 0.f, 0.f);
#pragma unroll 8
        for (int t = 0; t < PR_GROUP; t++) {
            float4 v = __ldcs(sb + (size_t)toks[t] * D4 + tid);
            acc.x += v.x; acc.y += v.y; acc.z += v.z; acc.w += v.w;
        }
        float4* part = reinterpret_cast<float4*>(g_partial);
        part[((size_t)b * PRCH + g) * D4 + tid] = acc;

        // last-block reduction
        __threadfence();
        if (tid == 0) ticket = atomicAdd(&g_count[b], 1);
        __syncthreads();
        if (ticket == PRCH - 1) {
            const float4* pbase = part + (size_t)b * PRCH * D4 + tid;
            float4 s = make_float4(0.f, 0.f, 0.f, 0.f);
#pragma unroll
            for (int c = 0; c < PRCH; c++) {
                float4 v = __ldcg(pbase + (size_t)c * D4);
                s.x += v.x; s.y += v.y; s.z += v.z; s.w += v.w;
            }
            const float scale = 0.05f / (2048.0f + 1e-10f);
            s.x *= scale; s.y *= scale; s.z *= scale; s.w *= scale;
            out[((size_t)b * (KK + 1) + KK) * D4 + tid] = s;
            if (tid == 0) g_count[b] = 0;   // reset for next graph replay
        }
    } else {
        // copy CTA: sorted positions [j0, j0+16)
        const int j0 = (g - PRCH) * GROUP;
        __shared__ int toks[GROUP];
        if (tid < GROUP) toks[tid] = g_sorted[b * NN + j0 + tid];
        __syncthreads();

        float4* dst = out + ((size_t)b * (KK + 1) + j0) * D4 + tid;
#pragma unroll
        for (int h = 0; h < 2; h++) {
            float4 v[8];
#pragma unroll
            for (int t = 0; t < 8; t++)
                v[t] = __ldcs(sb + (size_t)toks[h * 8 + t] * D4 + tid);
#pragma unroll
            for (int t = 0; t < 8; t++)
                __stcs(dst + (size_t)(h * 8 + t) * D4, v[t]);
        }
    }
}

// ---------------------------------------------------------------------------
extern "C" void kernel_launch(void* const* d_in, const int* in_sizes, int n_in,
                              void* d_out, int out_size) {
    const float* seq = (const float*)d_in[0];
    const float* attn_weights = (const float*)d_in[1];
    float* out = (float*)d_out;
    (void)in_sizes; (void)n_in; (void)out_size;

    dim3 sgrid(NRUNS, BB);                // (4, 16)
    sort_chunks_kernel<<<sgrid, 256>>>(attn_weights);

    dim3 rgrid(NN / 256, BB);             // (16, 16)
    rank_scatter_kernel<<<rgrid, 256>>>();

    dim3 fgrid(PRCH + SELGROUPS, BB);     // (160, 16)
    gather_sum_kernel<<<fgrid, 256>>>((const float4*)seq, (float4*)out);
}